// round 2
// baseline (speedup 1.0000x reference)
#include <cuda_runtime.h>
#include <math.h>

#define BATCH 1024
#define N 200
#define H 128
#define K_TOP 8000
#define NBINS 4096
#define MAXCAND 2048

// cross-kernel scratch: v[b][h] = sum_i u_i * h1[i][h]
__device__ float g_v[BATCH * H];

extern __shared__ float smem_dyn[];   // [0,25600): Y ; [25600,51200): scratch

__global__ __launch_bounds__(256, 1)
void fused_gcn_kernel(const float* __restrict__ x,
                      const float* __restrict__ W1,
                      const float* __restrict__ b1)
{
    const int b   = blockIdx.x;
    const int tid = threadIdx.x;
    const float* __restrict__ xb = x + (size_t)b * N * N;

    float* Y_s     = smem_dyn;           // 200*128 floats = 102400 B
    float* scratch = smem_dyn + 25600;   // 102400 B (hist+cand / W1 / x-slice)

    __shared__ float dinv_s[N];
    __shared__ float u_s[N];
    __shared__ float b1_s[H];
    __shared__ float xs2[64 * 33];       // phase-Y k-chunk staging (padded)
    __shared__ float vbuf[16 * H];       // jg x h reduction buffer
    __shared__ float t_sh;
    __shared__ int   binB_sh, r_sh, cnt_sh;

    // ---------------- Phase 0: exact k-th largest threshold ----------------
    unsigned int* hist = (unsigned int*)scratch;     // 4096 bins
    float*        cand = scratch + NBINS;            // up to MAXCAND

    for (int i = tid; i < NBINS; i += 256) hist[i] = 0u;
    __syncthreads();

    for (int e = tid; e < N * N; e += 256) {
        float vv = xb[e];
        int bin = (int)(vv * 4096.0f);
        bin = min(max(bin, 0), NBINS - 1);
        atomicAdd(&hist[bin], 1u);
    }
    __syncthreads();

    if (tid == 0) {
        int acc = 0, bsel = 0, r = 1;
        for (int bi = NBINS - 1; bi >= 0; --bi) {
            int nacc = acc + (int)hist[bi];
            if (nacc >= K_TOP) { bsel = bi; r = K_TOP - acc; break; }
            acc = nacc;
        }
        binB_sh = bsel; r_sh = r; cnt_sh = 0;
        t_sh = (float)bsel / 4096.0f;   // fallback (cand overflow, never expected)
    }
    __syncthreads();

    const int binB = binB_sh;
    for (int e = tid; e < N * N; e += 256) {
        float vv = xb[e];
        int bin = (int)(vv * 4096.0f);
        bin = min(max(bin, 0), NBINS - 1);
        if (bin == binB) {
            int p = atomicAdd(&cnt_sh, 1);
            if (p < MAXCAND) cand[p] = vv;
        }
    }
    __syncthreads();

    {
        const int m = min(cnt_sh, MAXCAND);
        const int r = r_sh;
        for (int ci = tid; ci < m; ci += 256) {
            float vv = cand[ci];
            int g = 0, eq = 0;
            for (int l = 0; l < m; ++l) {
                float c = cand[l];
                g  += (c > vv);
                eq += (c == vv);
            }
            if (g < r && g + eq >= r) t_sh = vv;   // unique value; benign race
        }
    }
    __syncthreads();
    const float t = t_sh;

    // ---------------- Phase 1: deg -> dinv (column sums) ----------------
    if (tid < N) {
        float acc = 0.f;
        #pragma unroll 4
        for (int i = 0; i < N; ++i) {
            float vv = xb[i * N + tid];
            if (vv >= t) acc += vv;
        }
        dinv_s[tid] = 1.0f / sqrtf(1.0f + acc);
    }
    if (tid < H) b1_s[tid] = b1[tid];
    __syncthreads();

    // ---------------- Phase 1b: u_i = dinv_i * (dinv_i + sum_j A_ij dinv_j) ----
    {
        const int warp = tid >> 5, lane = tid & 31;
        for (int row = warp; row < N; row += 8) {
            float acc = 0.f;
            for (int j = lane; j < N; j += 32) {
                float vv = xb[row * N + j];
                if (vv >= t) acc += vv * dinv_s[j];
            }
            #pragma unroll
            for (int off = 16; off; off >>= 1)
                acc += __shfl_xor_sync(0xffffffffu, acc, off);
            if (lane == 0) {
                float di = dinv_s[row];
                u_s[row] = di * (di + acc);
            }
        }
    }
    __syncthreads();

    // ---------------- Phase Y: Y = dinv_i * (x @ W1) ----------------
    float* W1_s = scratch;
    for (int e = tid; e < N * H; e += 256) W1_s[e] = W1[e];

    const int hg = tid & 15;       // 16 groups of 8 h-cols
    const int rg = tid >> 4;       // 16 groups of 4 rows (within 64-row block)
    const int h0 = hg * 8;

    for (int rb = 0; rb < 4; ++rb) {
        const int rows_in_block = (rb < 3) ? 64 : (N - 192);
        float acc[4][8];
        #pragma unroll
        for (int p = 0; p < 4; ++p)
            #pragma unroll
            for (int q = 0; q < 8; ++q) acc[p][q] = 0.f;

        for (int kc = 0; kc < N; kc += 32) {
            const int kw = min(32, N - kc);
            __syncthreads();
            for (int e = tid; e < 64 * 32; e += 256) {
                int rr = e >> 5, kk = e & 31;
                float vv = 0.f;
                if (rr < rows_in_block && kk < kw)
                    vv = xb[(rb * 64 + rr) * N + kc + kk];
                xs2[rr * 33 + kk] = vv;
            }
            __syncthreads();
            for (int kk = 0; kk < kw; ++kk) {
                const float4 w0 = *(const float4*)&W1_s[(kc + kk) * H + h0];
                const float4 w1 = *(const float4*)&W1_s[(kc + kk) * H + h0 + 4];
                #pragma unroll
                for (int p = 0; p < 4; ++p) {
                    float xv = xs2[(rg * 4 + p) * 33 + kk];
                    acc[p][0] += xv * w0.x; acc[p][1] += xv * w0.y;
                    acc[p][2] += xv * w0.z; acc[p][3] += xv * w0.w;
                    acc[p][4] += xv * w1.x; acc[p][5] += xv * w1.y;
                    acc[p][6] += xv * w1.z; acc[p][7] += xv * w1.w;
                }
            }
        }
        #pragma unroll
        for (int p = 0; p < 4; ++p) {
            int row = rb * 64 + rg * 4 + p;
            if (row < N) {
                float di = dinv_s[row];
                float4 o0 = make_float4(acc[p][0]*di, acc[p][1]*di, acc[p][2]*di, acc[p][3]*di);
                float4 o1 = make_float4(acc[p][4]*di, acc[p][5]*di, acc[p][6]*di, acc[p][7]*di);
                *(float4*)&Y_s[row * H + h0]     = o0;
                *(float4*)&Y_s[row * H + h0 + 4] = o1;
            }
        }
    }
    __syncthreads();

    // ---------------- Phase Z: Z = A^T Y + Y ; h1 = relu(dinv*Z + b1); v += u*h1 ----
    float* xsl = scratch;          // [200][64] masked x-slice
    const int jg  = tid >> 4;
    const int jl0 = jg * 4;

    float vloc[8];
    #pragma unroll
    for (int q = 0; q < 8; ++q) vloc[q] = 0.f;

    for (int jc = 0; jc < 4; ++jc) {
        const int jbase = jc * 64;
        const int jw    = (jc < 3) ? 64 : (N - 192);
        __syncthreads();
        for (int e = tid; e < N * 64; e += 256) {
            int i = e >> 6, j = e & 63;
            float vv = 0.f;
            if (j < jw) {
                float xv = xb[i * N + jbase + j];
                vv = (xv >= t) ? xv : 0.f;
            }
            xsl[e] = vv;
        }
        __syncthreads();

        float acc[4][8];
        #pragma unroll
        for (int p = 0; p < 4; ++p)
            #pragma unroll
            for (int q = 0; q < 8; ++q) acc[p][q] = 0.f;

        for (int i = 0; i < N; ++i) {
            float a0 = xsl[i * 64 + jl0 + 0];
            float a1 = xsl[i * 64 + jl0 + 1];
            float a2 = xsl[i * 64 + jl0 + 2];
            float a3 = xsl[i * 64 + jl0 + 3];
            if ((a0 != 0.f) | (a1 != 0.f) | (a2 != 0.f) | (a3 != 0.f)) {
                const float4 y0 = *(const float4*)&Y_s[i * H + h0];
                const float4 y1 = *(const float4*)&Y_s[i * H + h0 + 4];
                float yv[8] = {y0.x, y0.y, y0.z, y0.w, y1.x, y1.y, y1.z, y1.w};
                if (a0 != 0.f) {
                    #pragma unroll
                    for (int q = 0; q < 8; ++q) acc[0][q] += a0 * yv[q];
                }
                if (a1 != 0.f) {
                    #pragma unroll
                    for (int q = 0; q < 8; ++q) acc[1][q] += a1 * yv[q];
                }
                if (a2 != 0.f) {
                    #pragma unroll
                    for (int q = 0; q < 8; ++q) acc[2][q] += a2 * yv[q];
                }
                if (a3 != 0.f) {
                    #pragma unroll
                    for (int q = 0; q < 8; ++q) acc[3][q] += a3 * yv[q];
                }
            }
        }

        #pragma unroll
        for (int p = 0; p < 4; ++p) {
            int jl = jl0 + p;
            if (jl < jw) {
                int j = jbase + jl;
                float dj = dinv_s[j], uj = u_s[j];
                #pragma unroll
                for (int q = 0; q < 8; ++q) {
                    float z  = acc[p][q] + Y_s[j * H + h0 + q];   // +Y = self loop
                    float h1 = fmaxf(fmaf(dj, z, b1_s[h0 + q]), 0.f);
                    vloc[q]  = fmaf(uj, h1, vloc[q]);
                }
            }
        }
    }

    // reduce vloc over the 16 jg groups
    #pragma unroll
    for (int q = 0; q < 8; ++q) vbuf[jg * H + h0 + q] = vloc[q];
    __syncthreads();
    if (tid < H) {
        float s = 0.f;
        #pragma unroll
        for (int g = 0; g < 16; ++g) s += vbuf[g * H + tid];
        g_v[b * H + tid] = s;
    }
}

// res[b][h] = (1/N) * sum_f v[b][f] * W2[f][h] + b2[h]
__global__ __launch_bounds__(256)
void final_kernel(const float* __restrict__ W2,
                  const float* __restrict__ b2,
                  float* __restrict__ out)
{
    __shared__ float v_s[2][H];
    const int tid = threadIdx.x;
    const int b0  = blockIdx.x * 2;
    v_s[tid >> 7][tid & 127] = g_v[b0 * H + tid];
    __syncthreads();
    const int bb = tid >> 7;
    const int h  = tid & 127;
    float acc = 0.f;
    #pragma unroll 8
    for (int f = 0; f < H; ++f)
        acc += v_s[bb][f] * W2[f * H + h];
    out[(b0 + bb) * H + h] = acc * (1.0f / (float)N) + b2[h];
}

extern "C" void kernel_launch(void* const* d_in, const int* in_sizes, int n_in,
                              void* d_out, int out_size)
{
    const float* x  = (const float*)d_in[0];
    // d_in[1] = adj : unused (overwritten by sparse(x,0.2) in the reference)
    const float* W1 = (const float*)d_in[2];
    const float* b1 = (const float*)d_in[3];
    const float* W2 = (const float*)d_in[4];
    const float* b2 = (const float*)d_in[5];
    float* out = (float*)d_out;

    const int dyn = 51200 * (int)sizeof(float);   // 204800 B
    cudaFuncSetAttribute(fused_gcn_kernel,
                         cudaFuncAttributeMaxDynamicSharedMemorySize, dyn);

    fused_gcn_kernel<<<BATCH, 256, dyn>>>(x, W1, b1);
    final_kernel<<<BATCH / 2, 256>>>(W2, b2, out);
}

// round 3
// speedup vs baseline: 1.5249x; 1.5249x over previous
#include <cuda_runtime.h>
#include <math.h>

#define BATCH 1024
#define N 200
#define H 128
#define K_TOP 8000
#define NBINS 4096
#define MAXCAND 2048
#define XS_STRIDE 36   // 144B row stride: 16B-aligned for float4 staging

typedef unsigned long long ull;

__device__ float g_v[BATCH * H];

__device__ __forceinline__ void ffma2(ull &d, ull a, ull b) {
    asm("fma.rn.f32x2 %0, %1, %2, %0;" : "+l"(d) : "l"(a), "l"(b));
}
__device__ __forceinline__ ull pack2(float x) {
    ull r; unsigned xi = __float_as_uint(x);
    asm("mov.b64 %0, {%1, %1};" : "=l"(r) : "r"(xi));
    return r;
}
__device__ __forceinline__ float2 unpack2(ull v) {
    float2 f;
    asm("mov.b64 {%0, %1}, %2;" : "=f"(f.x), "=f"(f.y) : "l"(v));
    return f;
}
__device__ __forceinline__ ull mul2(ull a, ull b) {
    ull r; asm("mul.rn.f32x2 %0, %1, %2;" : "=l"(r) : "l"(a), "l"(b));
    return r;
}

extern __shared__ float smem_dyn[];   // [0,25600): Y_s ; [25600,51200): scratch

__global__ __launch_bounds__(512, 1)
void fused_gcn_kernel(const float* __restrict__ x,
                      const float* __restrict__ W1,
                      const float* __restrict__ b1)
{
    const int b    = blockIdx.x;
    const int tid  = threadIdx.x;
    const int warp = tid >> 5;
    const int lane = tid & 31;
    const float* __restrict__ xb = x + (size_t)b * N * N;

    float* Y_s     = smem_dyn;           // 200*128 fp32 = 102400 B
    float* scratch = smem_dyn + 25600;   // hist+cand, then W1_s (102400 B)

    __shared__ float dinv_s[N];
    __shared__ float u_s[N];
    __shared__ float b1_s[H];
    __shared__ float xs2[128 * XS_STRIDE];   // 18432 B; vbuf aliases this later
    __shared__ float t_sh;
    __shared__ int   binB_sh, r_sh, cnt_sh;

    // ---------------- Phase 0: exact k-th largest threshold ----------------
    unsigned int* hist = (unsigned int*)scratch;
    float*        cand = scratch + NBINS;

    for (int i = tid; i < NBINS; i += 512) hist[i] = 0u;
    __syncthreads();

    for (int e = tid; e < N * N; e += 512) {
        float vv = xb[e];
        int bin = (int)(vv * 4096.0f);
        bin = min(max(bin, 0), NBINS - 1);
        atomicAdd(&hist[bin], 1u);
    }
    __syncthreads();

    if (tid == 0) {
        int acc = 0, bsel = 0, r = 1;
        for (int bi = NBINS - 1; bi >= 0; --bi) {
            int nacc = acc + (int)hist[bi];
            if (nacc >= K_TOP) { bsel = bi; r = K_TOP - acc; break; }
            acc = nacc;
        }
        binB_sh = bsel; r_sh = r; cnt_sh = 0;
        t_sh = (float)bsel / 4096.0f;    // fallback, never expected
    }
    __syncthreads();

    const int binB = binB_sh;
    for (int e = tid; e < N * N; e += 512) {
        float vv = xb[e];
        int bin = (int)(vv * 4096.0f);
        bin = min(max(bin, 0), NBINS - 1);
        if (bin == binB) {
            int p = atomicAdd(&cnt_sh, 1);
            if (p < MAXCAND) cand[p] = vv;
        }
    }
    __syncthreads();

    {
        const int m = min(cnt_sh, MAXCAND);
        const int r = r_sh;
        for (int ci = tid; ci < m; ci += 512) {
            float vv = cand[ci];
            int g = 0, eq = 0;
            for (int l = 0; l < m; ++l) {
                float c = cand[l];
                g  += (c > vv);
                eq += (c == vv);
            }
            if (g < r && g + eq >= r) t_sh = vv;
        }
    }
    __syncthreads();
    const float t = t_sh;

    // ---------------- Phase 1: deg -> dinv (column sums, 2-way split) ------
    {
        const int col  = tid >> 1;
        const int half = tid & 1;
        float acc = 0.f;
        if (col < N) {
            const float* p = xb + half * 100 * N + col;
            #pragma unroll 10
            for (int i = 0; i < 100; ++i) {
                float vv = p[i * N];
                if (vv >= t) acc += vv;
            }
        }
        acc += __shfl_xor_sync(0xffffffffu, acc, 1);
        if (half == 0 && col < N) dinv_s[col] = rsqrtf(1.0f + acc);
    }
    if (tid < H) b1_s[tid] = b1[tid];
    __syncthreads();

    // ---------------- Phase 1b: u_i = dinv_i*(dinv_i + sum_j A_ij dinv_j) --
    for (int row = warp; row < N; row += 16) {
        float acc = 0.f;
        for (int j = lane; j < N; j += 32) {
            float vv = xb[row * N + j];
            if (vv >= t) acc += vv * dinv_s[j];
        }
        #pragma unroll
        for (int off = 16; off; off >>= 1)
            acc += __shfl_xor_sync(0xffffffffu, acc, off);
        if (lane == 0) {
            float di = dinv_s[row];
            u_s[row] = di * (di + acc);
        }
    }

    // Load W1 into scratch (sync inside GEMM loop makes it visible)
    {
        float4* w4s = (float4*)scratch;
        const float4* w4g = (const float4*)W1;
        for (int i = tid; i < N * H / 4; i += 512) w4s[i] = w4g[i];
    }

    const int hg  = tid & 15;       // 16 h-groups of 8 cols (4 packed)
    const int rgi = tid >> 4;       // 32 row-groups of 4 rows
    const int h0  = hg * 8;

    // ---------------- Phase Y: Y = dinv_i * (x @ W1) -----------------------
    for (int rb = 0; rb < 2; ++rb) {
        const int rbase = rb * 128;
        const int rows  = (rb == 0) ? 128 : (N - 128);   // 128, 72
        const bool act  = (rgi * 4) < rows;

        ull acc[4][4];
        #pragma unroll
        for (int p = 0; p < 4; ++p)
            #pragma unroll
            for (int q = 0; q < 4; ++q) acc[p][q] = 0ull;

        for (int kc = 0; kc < N; kc += 32) {
            const int kw = min(32, N - kc);
            __syncthreads();
            #pragma unroll
            for (int it = 0; it < 2; ++it) {
                int idx = tid + it * 512;
                int rr = idx >> 3, kq = idx & 7;
                float4 vv = make_float4(0.f, 0.f, 0.f, 0.f);
                if (rr < rows && kq * 4 < kw)
                    vv = *(const float4*)&xb[(rbase + rr) * N + kc + kq * 4];
                *(float4*)&xs2[rr * XS_STRIDE + kq * 4] = vv;
            }
            __syncthreads();
            if (act) {
                #pragma unroll 8
                for (int kk = 0; kk < kw; ++kk) {
                    const ull* wrow = (const ull*)&scratch[(kc + kk) * H + h0];
                    ull w0 = wrow[0], w1 = wrow[1], w2 = wrow[2], w3 = wrow[3];
                    #pragma unroll
                    for (int p = 0; p < 4; ++p) {
                        ull xv = pack2(xs2[(rgi * 4 + p) * XS_STRIDE + kk]);
                        ffma2(acc[p][0], xv, w0);
                        ffma2(acc[p][1], xv, w1);
                        ffma2(acc[p][2], xv, w2);
                        ffma2(acc[p][3], xv, w3);
                    }
                }
            }
        }
        if (act) {
            #pragma unroll
            for (int p = 0; p < 4; ++p) {
                int row = rbase + rgi * 4 + p;
                ull d2 = pack2(dinv_s[row]);
                #pragma unroll
                for (int q = 0; q < 4; ++q)
                    *(ull*)&Y_s[row * H + h0 + 2 * q] = mul2(acc[p][q], d2);
            }
        }
    }
    __syncthreads();

    // ------- Phase Z: Z = Am^T Y (+Y self-loop); h1=relu(dinv*Z+b1); v+=u*h1
    float vloc[8];
    #pragma unroll
    for (int q = 0; q < 8; ++q) vloc[q] = 0.f;

    for (int rb = 0; rb < 2; ++rb) {
        const int jbase = rb * 128;
        const int jrows = (rb == 0) ? 128 : (N - 128);
        const bool act  = (rgi * 4) < jrows;

        ull acc[4][4];
        #pragma unroll
        for (int p = 0; p < 4; ++p)
            #pragma unroll
            for (int q = 0; q < 4; ++q) acc[p][q] = 0ull;

        for (int kc = 0; kc < N; kc += 32) {
            const int kw = min(32, N - kc);
            __syncthreads();
            // stage masked transpose: xs2[j_local][kk] = mask(x[kc+kk][jbase+j_local])
            #pragma unroll
            for (int it = 0; it < 2; ++it) {
                int idx = tid + it * 512;
                int kk = idx >> 5, jq = idx & 31;
                if (kk < kw && jq * 4 + 3 < jrows) {
                    float4 vv = *(const float4*)&xb[(kc + kk) * N + jbase + jq * 4];
                    vv.x = (vv.x >= t) ? vv.x : 0.f;
                    vv.y = (vv.y >= t) ? vv.y : 0.f;
                    vv.z = (vv.z >= t) ? vv.z : 0.f;
                    vv.w = (vv.w >= t) ? vv.w : 0.f;
                    xs2[(jq * 4 + 0) * XS_STRIDE + kk] = vv.x;
                    xs2[(jq * 4 + 1) * XS_STRIDE + kk] = vv.y;
                    xs2[(jq * 4 + 2) * XS_STRIDE + kk] = vv.z;
                    xs2[(jq * 4 + 3) * XS_STRIDE + kk] = vv.w;
                }
            }
            __syncthreads();
            if (act) {
                #pragma unroll 8
                for (int kk = 0; kk < kw; ++kk) {
                    const ull* yrow = (const ull*)&Y_s[(kc + kk) * H + h0];
                    ull w0 = yrow[0], w1 = yrow[1], w2 = yrow[2], w3 = yrow[3];
                    #pragma unroll
                    for (int p = 0; p < 4; ++p) {
                        ull av = pack2(xs2[(rgi * 4 + p) * XS_STRIDE + kk]);
                        ffma2(acc[p][0], av, w0);
                        ffma2(acc[p][1], av, w1);
                        ffma2(acc[p][2], av, w2);
                        ffma2(acc[p][3], av, w3);
                    }
                }
            }
        }
        if (act) {
            #pragma unroll
            for (int p = 0; p < 4; ++p) {
                int j = jbase + rgi * 4 + p;
                float dj = dinv_s[j], uj = u_s[j];
                #pragma unroll
                for (int q = 0; q < 4; ++q) {
                    float2 z2 = unpack2(acc[p][q]);
                    int hh = h0 + 2 * q;
                    float z0 = z2.x + Y_s[j * H + hh];       // + self loop
                    float z1 = z2.y + Y_s[j * H + hh + 1];
                    float h1a = fmaxf(fmaf(dj, z0, b1_s[hh]),     0.f);
                    float h1b = fmaxf(fmaf(dj, z1, b1_s[hh + 1]), 0.f);
                    vloc[2 * q]     = fmaf(uj, h1a, vloc[2 * q]);
                    vloc[2 * q + 1] = fmaf(uj, h1b, vloc[2 * q + 1]);
                }
            }
        }
    }

    // ---------------- reduce vloc over row-groups --------------------------
    __syncthreads();                 // xs2 free now; reuse as vbuf
    float* vbuf = xs2;               // [16 warps][128]
    #pragma unroll
    for (int q = 0; q < 8; ++q)
        vloc[q] += __shfl_xor_sync(0xffffffffu, vloc[q], 16);
    if (lane < 16) {
        #pragma unroll
        for (int q = 0; q < 8; ++q)
            vbuf[warp * H + lane * 8 + q] = vloc[q];
    }
    __syncthreads();
    if (tid < H) {
        float s = 0.f;
        #pragma unroll
        for (int w = 0; w < 16; ++w) s += vbuf[w * H + tid];
        g_v[b * H + tid] = s;
    }
}

// res[b][h] = (1/N) * sum_f v[b][f] * W2[f][h] + b2[h]
__global__ __launch_bounds__(256)
void final_kernel(const float* __restrict__ W2,
                  const float* __restrict__ b2,
                  float* __restrict__ out)
{
    __shared__ float v_s[2][H];
    const int tid = threadIdx.x;
    const int b0  = blockIdx.x * 2;
    v_s[tid >> 7][tid & 127] = g_v[b0 * H + tid];
    __syncthreads();
    const int bb = tid >> 7;
    const int h  = tid & 127;
    float acc = 0.f;
    #pragma unroll 8
    for (int f = 0; f < H; ++f)
        acc += v_s[bb][f] * W2[f * H + h];
    out[(b0 + bb) * H + h] = acc * (1.0f / (float)N) + b2[h];
}

extern "C" void kernel_launch(void* const* d_in, const int* in_sizes, int n_in,
                              void* d_out, int out_size)
{
    const float* x  = (const float*)d_in[0];
    // d_in[1] = adj : unused (overwritten by sparse(x,0.2) in the reference)
    const float* W1 = (const float*)d_in[2];
    const float* b1 = (const float*)d_in[3];
    const float* W2 = (const float*)d_in[4];
    const float* b2 = (const float*)d_in[5];
    float* out = (float*)d_out;

    const int dyn = 51200 * (int)sizeof(float);   // 204800 B
    cudaFuncSetAttribute(fused_gcn_kernel,
                         cudaFuncAttributeMaxDynamicSharedMemorySize, dyn);

    fused_gcn_kernel<<<BATCH, 512, dyn>>>(x, W1, b1);
    final_kernel<<<BATCH / 2, 256>>>(W2, b2, out);
}